// round 3
// baseline (speedup 1.0000x reference)
#include <cuda_runtime.h>
#include <math.h>

#define IM    256
#define MTOT  184320
#define NSP   288
#define NSAM  640
#define ORTHO (1.0f/256.0f)

#define NCHUNK   96
#define M_PER_CH (MTOT/NCHUNK)   // 1920
#define MT       32              // m per adjoint stage
#define NSTAGES  (M_PER_CH/MT)   // 60

typedef unsigned long long u64;

// Scratch (static device arrays: allocation-free)
__device__ float2 g_G[MTOT*IM];          // k-space rows expanded over v  (377 MB)
__device__ float2 g_Xp[NCHUNK][IM*IM];   // adjoint partials              (50 MB)

__device__ __forceinline__ float2 cmulf(float2 a, float2 b) {
    return make_float2(a.x*b.x - a.y*b.y, a.x*b.y + a.y*b.x);
}
__device__ __forceinline__ u64 pk(float lo, float hi) {
    u64 r; asm("mov.b64 %0, {%1,%2};" : "=l"(r) : "f"(lo), "f"(hi)); return r;
}
__device__ __forceinline__ float2 unpk(u64 v) {
    float2 f; asm("mov.b64 {%0,%1}, %2;" : "=f"(f.x), "=f"(f.y) : "l"(v)); return f;
}
__device__ __forceinline__ u64 ffma2(u64 a, u64 b, u64 c) {
    u64 d; asm("fma.rn.f32x2 %0, %1, %2, %3;" : "=l"(d) : "l"(a), "l"(b), "l"(c)); return d;
}
__device__ __forceinline__ u64 fmul2(u64 a, u64 b) {
    u64 d; asm("mul.rn.f32x2 %0, %1, %2;" : "=l"(d) : "l"(a), "l"(b)); return d;
}

// ---------------------------------------------------------------------------
// Forward: per block 32 m. Thread: vg = tid&31 (v lanes), mg = tid>>5
// (8 groups x 4 m). Accumulates T[m, vg+32j], j=0..7, over all 256 u.
// Packed-f32x2 complex MAC: acc += (e.x,e.x)*(c.x,c.y) + (e.y,e.y)*(-c.y,c.x)
// with phase recurrence kept in broadcast-packed registers:
//   e'.x = st.x*e.x - st.y*e.y ;  e'.y = st.y*e.x + st.x*e.y
// Dynamic smem: imgA[16][256] = (c.x,c.y), imgB[16][256] = (-c.y,c.x).
// ---------------------------------------------------------------------------
__global__ __launch_bounds__(256)
void fwd_kernel(const float2* __restrict__ img,
                const float2* __restrict__ yrad,
                const float*  __restrict__ lamp,
                const float*  __restrict__ kxs,
                const float*  __restrict__ kys)
{
    extern __shared__ u64 smf[];
    u64* imgA = smf;            // 4096 entries
    u64* imgB = smf + 4096;

    const int tid = threadIdx.x;
    const int vg  = tid & 31;
    const int mg  = tid >> 5;
    const int m0  = blockIdx.x * 32 + mg * 4;

    float kx[4], ky[4];
    u64 exx[4], eyy[4];          // broadcast-packed phase state
    u64 STX[4], STYP[4], STY[4]; // st.x, -st.y, st.y (broadcast-packed)
#pragma unroll
    for (int i = 0; i < 4; i++) {
        kx[i] = kxs[m0 + i];
        ky[i] = kys[m0 + i];
        float s, c;
        sincosf(128.0f * kx[i], &s, &c);   // e^{-i kx * (-128)}
        exx[i] = pk(c, c);
        eyy[i] = pk(s, s);
        sincosf(kx[i], &s, &c);            // step st = e^{-i kx} = (c, -s)
        STX [i] = pk(c, c);                // st.x
        STYP[i] = pk(s, s);                // -st.y = +s
        STY [i] = pk(-s, -s);              // st.y = -s
    }

    u64 acc[4][8];
#pragma unroll
    for (int i = 0; i < 4; i++)
#pragma unroll
        for (int j = 0; j < 8; j++) acc[i][j] = 0ull;

    for (int ub = 0; ub < IM; ub += 16) {
        __syncthreads();
#pragma unroll
        for (int r = 0; r < 16; r++) {
            int idx = r * 256 + tid;
            float2 c = img[(ub + (idx >> 8)) * IM + (idx & 255)];
            imgA[idx] = pk(c.x, c.y);
            imgB[idx] = pk(-c.y, c.x);
        }
        __syncthreads();
#pragma unroll
        for (int uu = 0; uu < 16; uu++) {
            u64 ca[8], cb[8];
#pragma unroll
            for (int j = 0; j < 8; j++) {
                ca[j] = imgA[uu * 256 + vg + 32 * j];
                cb[j] = imgB[uu * 256 + vg + 32 * j];
            }
#pragma unroll
            for (int i = 0; i < 4; i++) {
#pragma unroll
                for (int j = 0; j < 8; j++) {
                    acc[i][j] = ffma2(exx[i], ca[j], acc[i][j]);
                    acc[i][j] = ffma2(eyy[i], cb[j], acc[i][j]);
                }
                // e' = e * st:
                //   nx = st.x*e.x + (-st.y)*e.y
                //   ny = st.y*e.x +  st.x *e.y
                u64 nx = ffma2(STX[i], exx[i], fmul2(STYP[i], eyy[i]));
                u64 ny = ffma2(STY[i], exx[i], fmul2(STX [i], eyy[i]));
                exx[i] = nx; eyy[i] = ny;
            }
        }
    }

    const float lam = 1.0f / (1.0f + expf(-lamp[0]));
    const float vgc = (float)(vg - 128);

#pragma unroll
    for (int i = 0; i < 4; i++) {
        const int m = m0 + i;
        float s, c;
        sincosf(ky[i] * vgc, &s, &c);
        const float2 eyb = make_float2(c, -s);     // e^{-i ky (vg-128)}
        sincosf(ky[i] * 32.0f, &s, &c);
        const float2 eys = make_float2(c, -s);     // e^{-i 32 ky}

        float2 t = make_float2(0.f, 0.f);
        float2 e = eyb;
#pragma unroll
        for (int j = 0; j < 8; j++) {
            float2 a = unpk(acc[i][j]);
            t.x = fmaf(a.x, e.x, fmaf(-a.y, e.y, t.x));
            t.y = fmaf(a.x, e.y, fmaf( a.y, e.x, t.y));
            e = cmulf(e, eys);
        }
#pragma unroll
        for (int o = 16; o > 0; o >>= 1) {
            t.x += __shfl_xor_sync(0xffffffffu, t.x, o);
            t.y += __shfl_xor_sync(0xffffffffu, t.y, o);
        }

        const float dcf = sqrtf(kx[i]*kx[i] + ky[i]*ky[i]);
        const int   sp  = m / NSAM;
        const int   sam = m - sp * NSAM;
        const float2 y  = yrad[sam * NSP + sp];
        const float  w  = lam * dcf * ORTHO;
        const float2 k  = make_float2(fmaf(w, t.x, (1.0f - lam) * y.x),
                                      fmaf(w, t.y, (1.0f - lam) * y.y));

        // expand G[m, v] = k * e^{+i ky (v-128)}
        float2 cur = make_float2(eyb.x, -eyb.y);
        const float2 esp = make_float2(eys.x, -eys.y);
#pragma unroll
        for (int j = 0; j < 8; j++) {
            g_G[m * IM + vg + 32 * j] = cmulf(k, cur);
            cur = cmulf(cur, esp);
        }
    }
}

// ---------------------------------------------------------------------------
// Adjoint: X[u,v] = sum_m e^{+i kx_m (u-128)} * G[m,v].
// Block = (chunk, u-tile 64, v-tile 128). Thread: ug = tid>>4 (4 u each),
// vg = tid&15 (8 v strided 16). Packed complex MAC:
//   acc += (e.x,e.x)*(g.x,g.y) + (e.y,e.y)*(-g.y,g.x)
// Dynamic smem: EsXX/EsYY [32][64] broadcast pairs, Gs/Gsn [32][128].
// ---------------------------------------------------------------------------
__global__ __launch_bounds__(256)
void adj_kernel(const float* __restrict__ kxs)
{
    extern __shared__ u64 sma[];
    u64* EsXX = sma;                  // 32*64 = 2048
    u64* EsYY = sma + 2048;
    u64* Gs   = sma + 4096;           // 32*128 = 4096
    u64* Gsn  = sma + 8192;

    const int tid   = threadIdx.x;
    const int vg    = tid & 15;
    const int ug    = tid >> 4;
    const int chunk = blockIdx.x;
    const int u0    = blockIdx.y * 64;
    const int v0    = blockIdx.z * 128;
    const int mbase = chunk * M_PER_CH;

    u64 acc[4][8];
#pragma unroll
    for (int i = 0; i < 4; i++)
#pragma unroll
        for (int j = 0; j < 8; j++) acc[i][j] = 0ull;

    for (int st = 0; st < NSTAGES; st++) {
        const int ms0 = mbase + st * MT;
        __syncthreads();
        // stage G tile: 32 m x 128 v, two layouts
#pragma unroll
        for (int r = 0; r < 16; r++) {
            int idx = r * 256 + tid;
            int mm  = idx >> 7, vv = idx & 127;
            float2 g = g_G[(ms0 + mm) * IM + v0 + vv];
            Gs [mm * 128 + vv] = pk(g.x, g.y);
            Gsn[mm * 128 + vv] = pk(-g.y, g.x);
        }
        // stage phase tile: 32 m x 64 u via recurrence (8 u per thread)
        {
            const int mm  = tid >> 3;
            const int us0 = (tid & 7) * 8;
            const float kxv = kxs[ms0 + mm];
            float s, c;
            sincosf(kxv * (float)(u0 + us0 - 128), &s, &c);
            float2 cur = make_float2(c, s);          // e^{+i kx uc}
            sincosf(kxv, &s, &c);
            const float2 stp = make_float2(c, s);    // e^{+i kx}
#pragma unroll
            for (int q = 0; q < 8; q++) {
                EsXX[mm * 64 + us0 + q] = pk(cur.x, cur.x);
                EsYY[mm * 64 + us0 + q] = pk(cur.y, cur.y);
                cur = cmulf(cur, stp);
            }
        }
        __syncthreads();

#pragma unroll 2
        for (int mm = 0; mm < MT; mm++) {
            u64 exx[4], eyy[4], gv[8], gvn[8];
#pragma unroll
            for (int i = 0; i < 4; i++) {
                exx[i] = EsXX[mm * 64 + ug * 4 + i];
                eyy[i] = EsYY[mm * 64 + ug * 4 + i];
            }
#pragma unroll
            for (int j = 0; j < 8; j++) {
                gv [j] = Gs [mm * 128 + vg + 16 * j];
                gvn[j] = Gsn[mm * 128 + vg + 16 * j];
            }
#pragma unroll
            for (int i = 0; i < 4; i++)
#pragma unroll
                for (int j = 0; j < 8; j++) {
                    acc[i][j] = ffma2(exx[i], gv[j], acc[i][j]);
                    acc[i][j] = ffma2(eyy[i], gvn[j], acc[i][j]);
                }
        }
    }

#pragma unroll
    for (int i = 0; i < 4; i++) {
        const int u = u0 + ug * 4 + i;
#pragma unroll
        for (int j = 0; j < 8; j++) {
            const int v = v0 + vg + 16 * j;
            g_Xp[chunk][u * IM + v] = unpk(acc[i][j]);
        }
    }
}

// ---------------------------------------------------------------------------
// Reduce partials, scale, write (H,W,2) interleaved output.
// ---------------------------------------------------------------------------
__global__ __launch_bounds__(256)
void reduce_kernel(float* __restrict__ out)
{
    const int i = blockIdx.x * 256 + threadIdx.x;
    float sx = 0.f, sy = 0.f;
#pragma unroll 8
    for (int c = 0; c < NCHUNK; c++) {
        float2 p = g_Xp[c][i];
        sx += p.x; sy += p.y;
    }
    out[2*i + 0] = sx * ORTHO;
    out[2*i + 1] = sy * ORTHO;
}

// ---------------------------------------------------------------------------
extern "C" void kernel_launch(void* const* d_in, const int* in_sizes, int n_in,
                              void* d_out, int out_size)
{
    const float2* img  = (const float2*)d_in[0];
    const float2* yrad = (const float2*)d_in[1];
    const float*  lamp = (const float*)d_in[2];
    const float*  ktr  = (const float*)d_in[3];
    const float*  kxs  = ktr;
    const float*  kys  = ktr + MTOT;
    float* out = (float*)d_out;

    const int FWD_SMEM = 2 * 4096 * (int)sizeof(u64);   // 64 KB
    const int ADJ_SMEM = 12288 * (int)sizeof(u64);      // 96 KB
    cudaFuncSetAttribute(fwd_kernel, cudaFuncAttributeMaxDynamicSharedMemorySize, FWD_SMEM);
    cudaFuncSetAttribute(adj_kernel, cudaFuncAttributeMaxDynamicSharedMemorySize, ADJ_SMEM);

    fwd_kernel<<<MTOT/32, 256, FWD_SMEM>>>(img, yrad, lamp, kxs, kys);

    dim3 agrid(NCHUNK, IM/64, IM/128);
    adj_kernel<<<agrid, 256, ADJ_SMEM>>>(kxs);

    reduce_kernel<<<IM*IM/256, 256>>>(out);
}

// round 4
// speedup vs baseline: 1.0452x; 1.0452x over previous
#include <cuda_runtime.h>
#include <math.h>

#define IM    256
#define MTOT  184320
#define NSP   288
#define NSAM  640
#define ORTHO (1.0f/256.0f)

#define NCHUNK   96
#define M_PER_CH (MTOT/NCHUNK)   // 1920
#define MT       32              // m per adjoint stage
#define NSTAGES  (M_PER_CH/MT)   // 60
#define FWD_M    16              // m per forward block

typedef unsigned long long u64;

// Scratch (static device arrays: allocation-free)
__device__ float2 g_G[MTOT*IM];          // k-space rows expanded over v  (377 MB)
__device__ float2 g_Xp[NCHUNK][IM*IM];   // adjoint partials              (50 MB)

__device__ __forceinline__ float2 cmulf(float2 a, float2 b) {
    return make_float2(a.x*b.x - a.y*b.y, a.x*b.y + a.y*b.x);
}
__device__ __forceinline__ u64 pk(float lo, float hi) {
    u64 r; asm("mov.b64 %0, {%1,%2};" : "=l"(r) : "f"(lo), "f"(hi)); return r;
}
__device__ __forceinline__ float2 unpk(u64 v) {
    float2 f; asm("mov.b64 {%0,%1}, %2;" : "=f"(f.x), "=f"(f.y) : "l"(v)); return f;
}
__device__ __forceinline__ u64 ffma2(u64 a, u64 b, u64 c) {
    u64 d; asm("fma.rn.f32x2 %0, %1, %2, %3;" : "=l"(d) : "l"(a), "l"(b), "l"(c)); return d;
}

// ---------------------------------------------------------------------------
// Forward. Block: 16 m over full 256x256 image. Thread: vg = tid&63 (64 v
// lanes x 4 j, stride 64), mg = tid>>6 (4 groups x 4 m).
// P/Q split packed MAC: P[i][j] += (e.x,e.x)*(c.x,c.y),
//                       Q[i][j] += (e.y,e.y)*(c.x,c.y);  combine at end.
// Phases e^{-i kx (u-128)} staged per 16-u block via direct sincos (one per
// thread), read back as broadcast LDS.64. Single smem image layout.
// ---------------------------------------------------------------------------
__global__ __launch_bounds__(256, 2)
void fwd_kernel(const float2* __restrict__ img,
                const float2* __restrict__ yrad,
                const float*  __restrict__ lamp,
                const float*  __restrict__ kxs,
                const float*  __restrict__ kys)
{
    extern __shared__ u64 smf[];
    u64*    imgA = smf;               // 16 u x 256 v = 4096
    u64*    EsXX = smf + 4096;        // 16 m x 16 u  = 256
    u64*    EsYY = smf + 4352;        // 256
    float2* red  = (float2*)(smf + 4608);  // 8 warps x 4 i

    const int tid = threadIdx.x;
    const int vg  = tid & 63;
    const int mg  = tid >> 6;
    const int wid = tid >> 5;
    const int m0  = blockIdx.x * FWD_M;

    // phase staging constants for this thread's (mm, uu) slot
    const int   smm = tid >> 4;
    const int   suu = tid & 15;
    const float skx = kxs[m0 + smm];

    u64 P[4][4], Q[4][4];
#pragma unroll
    for (int i = 0; i < 4; i++)
#pragma unroll
        for (int j = 0; j < 4; j++) { P[i][j] = 0ull; Q[i][j] = 0ull; }

    for (int ub = 0; ub < IM; ub += 16) {
        __syncthreads();
        // stage image tile (single layout)
#pragma unroll
        for (int r = 0; r < 16; r++) {
            int idx = r * 256 + tid;
            float2 c = img[(ub + (idx >> 8)) * IM + (idx & 255)];
            imgA[idx] = pk(c.x, c.y);
        }
        // stage phase tile: e = e^{-i kx (ub+uu-128)} (direct sincos)
        {
            float s, c;
            sincosf(skx * (float)(ub + suu - 128), &s, &c);
            EsXX[tid] = pk(c, c);
            EsYY[tid] = pk(-s, -s);
        }
        __syncthreads();

#pragma unroll
        for (int uu = 0; uu < 16; uu++) {
            u64 ca[4];
#pragma unroll
            for (int j = 0; j < 4; j++) ca[j] = imgA[uu * 256 + vg + 64 * j];
#pragma unroll
            for (int i = 0; i < 4; i++) {
                const int eidx = (mg * 4 + i) * 16 + uu;
                u64 exx = EsXX[eidx];
                u64 eyy = EsYY[eidx];
#pragma unroll
                for (int j = 0; j < 4; j++) {
                    P[i][j] = ffma2(exx, ca[j], P[i][j]);
                    Q[i][j] = ffma2(eyy, ca[j], Q[i][j]);
                }
            }
        }
    }

    const float lam = 1.0f / (1.0f + expf(-lamp[0]));
    const float vgc = (float)(vg - 128);

    // pass 1: Ey-weighted partial sums, warp-reduce, stash per-warp sums
#pragma unroll
    for (int i = 0; i < 4; i++) {
        const int m = m0 + mg * 4 + i;
        const float kyv = kys[m];
        float s, c;
        sincosf(kyv * vgc, &s, &c);
        float2 e = make_float2(c, -s);              // e^{-i ky (vg-128)}
        sincosf(kyv * 64.0f, &s, &c);
        const float2 eys = make_float2(c, -s);      // e^{-i 64 ky}

        float2 t = make_float2(0.f, 0.f);
#pragma unroll
        for (int j = 0; j < 4; j++) {
            float2 Pj = unpk(P[i][j]);
            float2 Qj = unpk(Q[i][j]);
            float2 a  = make_float2(Pj.x - Qj.y, Pj.y + Qj.x);   // T[m, v_j]
            t.x = fmaf(a.x, e.x, fmaf(-a.y, e.y, t.x));
            t.y = fmaf(a.x, e.y, fmaf( a.y, e.x, t.y));
            e = cmulf(e, eys);
        }
#pragma unroll
        for (int o = 16; o > 0; o >>= 1) {
            t.x += __shfl_xor_sync(0xffffffffu, t.x, o);
            t.y += __shfl_xor_sync(0xffffffffu, t.y, o);
        }
        if ((tid & 31) == 0) red[wid * 4 + i] = t;
    }
    __syncthreads();

    // pass 2: combine warp pair, blend, expand G row
#pragma unroll
    for (int i = 0; i < 4; i++) {
        const int m = m0 + mg * 4 + i;
        float2 ta = red[(2 * mg    ) * 4 + i];
        float2 tb = red[(2 * mg + 1) * 4 + i];
        float2 t  = make_float2(ta.x + tb.x, ta.y + tb.y);

        const float kxv = kxs[m];
        const float kyv = kys[m];
        const float dcf = sqrtf(kxv * kxv + kyv * kyv);
        const int   sp  = m / NSAM;
        const int   sam = m - sp * NSAM;
        const float2 y  = yrad[sam * NSP + sp];
        const float  w  = lam * dcf * ORTHO;
        const float2 k  = make_float2(fmaf(w, t.x, (1.0f - lam) * y.x),
                                      fmaf(w, t.y, (1.0f - lam) * y.y));

        // G[m, v] = k * e^{+i ky (v-128)}, v = vg + 64 j
        float s, c;
        sincosf(kyv * vgc, &s, &c);
        float2 cur = make_float2(c, s);             // e^{+i ky (vg-128)}
        sincosf(kyv * 64.0f, &s, &c);
        const float2 esp = make_float2(c, s);       // e^{+i 64 ky}
#pragma unroll
        for (int j = 0; j < 4; j++) {
            g_G[m * IM + vg + 64 * j] = cmulf(k, cur);
            cur = cmulf(cur, esp);
        }
    }
}

// ---------------------------------------------------------------------------
// Adjoint: X[u,v] = sum_m e^{+i kx_m (u-128)} * G[m,v].
// Block = (u-tile 32, v-tile 128, chunk) — chunk slowest so the 16 blocks
// sharing one chunk's G slice are launch-adjacent (L2 reuse).
// Thread: ug = tid>>5 (warp, 4 u each), vg = tid&31 (4 v, stride 32).
// P/Q split, single G layout, phases staged via short recurrence.
// ---------------------------------------------------------------------------
__global__ __launch_bounds__(256, 2)
void adj_kernel(const float* __restrict__ kxs)
{
    extern __shared__ u64 sma[];
    u64* EsXX = sma;                  // 32 m x 32 u = 1024
    u64* EsYY = sma + 1024;
    u64* Gs   = sma + 2048;           // 32 m x 128 v = 4096

    const int tid   = threadIdx.x;
    const int vg    = tid & 31;
    const int ug    = tid >> 5;
    const int u0    = blockIdx.x * 32;
    const int v0    = blockIdx.y * 128;
    const int chunk = blockIdx.z;
    const int mbase = chunk * M_PER_CH;

    // staging slot for phases: mm = tid>>3, 4 u's starting at (tid&7)*4
    const int smm = tid >> 3;
    const int su0 = (tid & 7) * 4;

    u64 P[4][4], Q[4][4];
#pragma unroll
    for (int i = 0; i < 4; i++)
#pragma unroll
        for (int j = 0; j < 4; j++) { P[i][j] = 0ull; Q[i][j] = 0ull; }

    for (int st = 0; st < NSTAGES; st++) {
        const int ms0 = mbase + st * MT;
        __syncthreads();
        // stage G tile (single layout): 32 m x 128 v
#pragma unroll
        for (int r = 0; r < 16; r++) {
            int idx = r * 256 + tid;
            float2 g = g_G[(ms0 + (idx >> 7)) * IM + v0 + (idx & 127)];
            Gs[idx] = pk(g.x, g.y);
        }
        // stage phase tile: e^{+i kx (u-128)}, 4 u per thread via recurrence
        {
            const float kxv = kxs[ms0 + smm];
            float s, c;
            sincosf(kxv * (float)(u0 + su0 - 128), &s, &c);
            float2 cur = make_float2(c, s);
            sincosf(kxv, &s, &c);
            const float2 stp = make_float2(c, s);
#pragma unroll
            for (int q = 0; q < 4; q++) {
                EsXX[smm * 32 + su0 + q] = pk(cur.x, cur.x);
                EsYY[smm * 32 + su0 + q] = pk(cur.y, cur.y);
                cur = cmulf(cur, stp);
            }
        }
        __syncthreads();

#pragma unroll 2
        for (int mm = 0; mm < MT; mm++) {
            u64 gv[4];
#pragma unroll
            for (int j = 0; j < 4; j++) gv[j] = Gs[mm * 128 + vg + 32 * j];
#pragma unroll
            for (int i = 0; i < 4; i++) {
                u64 exx = EsXX[mm * 32 + ug * 4 + i];
                u64 eyy = EsYY[mm * 32 + ug * 4 + i];
#pragma unroll
                for (int j = 0; j < 4; j++) {
                    P[i][j] = ffma2(exx, gv[j], P[i][j]);
                    Q[i][j] = ffma2(eyy, gv[j], Q[i][j]);
                }
            }
        }
    }

#pragma unroll
    for (int i = 0; i < 4; i++) {
        const int u = u0 + ug * 4 + i;
#pragma unroll
        for (int j = 0; j < 4; j++) {
            const int v = v0 + vg + 32 * j;
            float2 Pj = unpk(P[i][j]);
            float2 Qj = unpk(Q[i][j]);
            g_Xp[chunk][u * IM + v] = make_float2(Pj.x - Qj.y, Pj.y + Qj.x);
        }
    }
}

// ---------------------------------------------------------------------------
// Reduce partials, scale, write (H,W,2) interleaved output.
// ---------------------------------------------------------------------------
__global__ __launch_bounds__(256)
void reduce_kernel(float* __restrict__ out)
{
    const int i = blockIdx.x * 256 + threadIdx.x;
    float sx = 0.f, sy = 0.f;
#pragma unroll 8
    for (int c = 0; c < NCHUNK; c++) {
        float2 p = g_Xp[c][i];
        sx += p.x; sy += p.y;
    }
    out[2*i + 0] = sx * ORTHO;
    out[2*i + 1] = sy * ORTHO;
}

// ---------------------------------------------------------------------------
extern "C" void kernel_launch(void* const* d_in, const int* in_sizes, int n_in,
                              void* d_out, int out_size)
{
    const float2* img  = (const float2*)d_in[0];
    const float2* yrad = (const float2*)d_in[1];
    const float*  lamp = (const float*)d_in[2];
    const float*  ktr  = (const float*)d_in[3];
    const float*  kxs  = ktr;
    const float*  kys  = ktr + MTOT;
    float* out = (float*)d_out;

    const int FWD_SMEM = 4608 * (int)sizeof(u64) + 32 * (int)sizeof(float2); // ~37 KB
    const int ADJ_SMEM = 6144 * (int)sizeof(u64);                            // 48 KB
    cudaFuncSetAttribute(fwd_kernel, cudaFuncAttributeMaxDynamicSharedMemorySize, FWD_SMEM);
    cudaFuncSetAttribute(adj_kernel, cudaFuncAttributeMaxDynamicSharedMemorySize, ADJ_SMEM);

    fwd_kernel<<<MTOT/FWD_M, 256, FWD_SMEM>>>(img, yrad, lamp, kxs, kys);

    dim3 agrid(IM/32, IM/128, NCHUNK);   // chunk slowest -> L2 reuse of G slice
    adj_kernel<<<agrid, 256, ADJ_SMEM>>>(kxs);

    reduce_kernel<<<IM*IM/256, 256>>>(out);
}